// round 14
// baseline (speedup 1.0000x reference)
#include <cuda_runtime.h>
#include <cuda_bf16.h>
#include <math.h>

#define NN 8192
#define EE 262144
#define INC 64
#define DK 192      // IN_C*K = OUT_C*K
#define GG 64
#define NC 10
#define NEG_HUGE (-3.402823466e38f)

// ---------------- static scratch ----------------
__device__ int   g_is64;                  // 1 if index tensors are int64, 0 if int32
__device__ int   g_degi[NN];
__device__ float g_dinv[NN];
__device__ int   g_rowstart[NN + 1];
__device__ int   g_rowpos[NN];
__device__ int   g_gstart[GG];            // first row of each graph (NN if empty)
__device__ __align__(16) int   g_col[EE];
__device__ __align__(16) float g_H2[NN * INC];
__device__ __align__(16) float g_H3[NN * INC];
__device__ __align__(16) float g_H[NN * DK];
__device__ __align__(16) float g_Wmt[DK * DK];   // transposed masked/scaled weight [k][o]
__device__ float g_csum[DK], g_csumsq[DK];
__device__ __align__(16) float g_Hg[GG * 576];
__device__ __align__(16) float g_w1t[576 * 384];
__device__ __align__(16) float g_w2t[384 * 192];

// index accessor: handles both int32 and int64 on-disk layouts
__device__ __forceinline__ int idx_at(const void* p, long long i) {
    if (g_is64) return (int)(((const long long*)p)[i]);
    return ((const int*)p)[i];
}

// load 4 consecutive indices starting at 4-aligned element e0
__device__ __forceinline__ void idx4_at(const void* p, long long e0, int* o) {
    if (g_is64) {
        const longlong2* q = (const longlong2*)((const long long*)p + e0);
        longlong2 a = q[0], b = q[1];
        o[0] = (int)a.x; o[1] = (int)a.y; o[2] = (int)b.x; o[3] = (int)b.y;
    } else {
        int4 a = *(const int4*)((const int*)p + e0);
        o[0] = a.x; o[1] = a.y; o[2] = a.z; o[3] = a.w;
    }
}

// ================= K1: prep =================
// blocks 0..47: zero scratch; all blocks: strided w1/w2 transpose;
// block 48: dtype detect; block 49: spectral-norm + mask -> g_Wmt.
#define TW_TOTAL (384 * 576 + 192 * 384)   // 294912
__global__ void prep_kernel(const void* __restrict__ ei,
                            const float* __restrict__ W, const float* __restrict__ u,
                            const float* __restrict__ w1, const float* __restrict__ w2) {
    __shared__ float v[DK];
    __shared__ float red[256];
    __shared__ float s_nrm, s_inv;
    int blk = blockIdx.x, t = threadIdx.x;

    for (int idx = blk * 256 + t; idx < TW_TOTAL; idx += gridDim.x * 256) {
        if (idx < 384 * 576) {
            int o = idx / 576, k = idx - o * 576;
            g_w1t[k * 384 + o] = w1[idx];
        } else {
            int j = idx - 384 * 576;
            int o = j / 384, k = j - o * 384;
            g_w2t[k * 192 + o] = w2[j];
        }
    }

    if (blk < 48) {
        int i = blk * 256 + t;
        if (i < NN) { g_degi[i] = 0; g_rowpos[i] = 0; }
        if (i < DK) { g_csum[i] = 0.f; g_csumsq[i] = 0.f; }
        if (i < GG) g_gstart[i] = NN;
    } else if (blk == 48) {
        if (t == 0) {
            const int* p = (const int*)ei;
            int zeros = 0;
            for (int i = 0; i < 64; i++)
                if (p[2 * i + 1] == 0) zeros++;
            g_is64 = (zeros >= 48) ? 1 : 0;
        }
    } else if (blk == 49) {
        // ---- wprep: v = W^T u ; normalize ; sigma = u.(W v) ; masked scale ----
        if (t < DK) {
            float a = 0.f;
            for (int i = 0; i < DK; i++) a += W[i * DK + t] * u[i];
            v[t] = a;
        }
        __syncthreads();
        red[t] = (t < DK) ? v[t] * v[t] : 0.f;
        __syncthreads();
        for (int s = 128; s > 0; s >>= 1) { if (t < s) red[t] += red[t + s]; __syncthreads(); }
        if (t == 0) s_nrm = sqrtf(red[0]) + 1e-12f;
        __syncthreads();
        if (t < DK) v[t] /= s_nrm;
        __syncthreads();
        float p = 0.f;
        if (t < DK) {
            float a = 0.f;
            for (int j = 0; j < DK; j++) a += W[t * DK + j] * v[j];
            p = a * u[t];
        }
        red[t] = p;
        __syncthreads();
        for (int s = 128; s > 0; s >>= 1) { if (t < s) red[t] += red[t + s]; __syncthreads(); }
        if (t == 0) s_inv = 1.0f / red[0];
        __syncthreads();
        for (int idx = t; idx < DK * DK; idx += 256) {
            int o = idx / DK, k = idx - o * DK;
            float mv = (k < 64 * ((o >> 6) + 1)) ? W[idx] * s_inv : 0.f;
            g_Wmt[k * DK + o] = mv;
        }
    }
}

// ================= K2: degrees + graph boundaries (4 edges/thread) =========
__global__ void deg_kernel(const void* __restrict__ ei, const void* __restrict__ batch) {
    int tid = blockIdx.x * 256 + threadIdx.x;     // EE/4 threads
    int e0 = tid * 4;
    int r[4];
    idx4_at(ei, e0, r);
    #pragma unroll
    for (int i = 0; i < 4; i++) atomicAdd(&g_degi[r[i]], 1);
    if (tid < NN / 4) {
        int n0 = tid * 4;
        int b[4];
        idx4_at(batch, n0, b);
        int prev = (n0 == 0) ? -1 : idx_at(batch, n0 - 1);
        #pragma unroll
        for (int i = 0; i < 4; i++) {
            if (b[i] != prev) g_gstart[b[i]] = n0 + i;
            prev = b[i];
        }
    }
}

// ================= K3: scan + dinv (1 block, 1024 threads) =================
__global__ void scan_kernel() {
    __shared__ int sh[1024];
    int t = threadIdx.x;
    int base = t * 8;
    int loc[8];
    int s = 0;
    #pragma unroll
    for (int i = 0; i < 8; i++) {
        int d = g_degi[base + i];
        loc[i] = s; s += d;
        g_dinv[base + i] = (d > 0) ? rsqrtf((float)d) : 0.f;
    }
    sh[t] = s;
    __syncthreads();
    for (int off = 1; off < 1024; off <<= 1) {
        int v = (t >= off) ? sh[t - off] : 0;
        __syncthreads();
        sh[t] += v;
        __syncthreads();
    }
    int offset = (t > 0) ? sh[t - 1] : 0;
    #pragma unroll
    for (int i = 0; i < 8; i++) g_rowstart[base + i] = offset + loc[i];
    if (t == 1023) g_rowstart[NN] = sh[1023];
}

// ================= K4: CSR build, col only (4 edges/thread) =================
__global__ void csr_kernel(const void* __restrict__ ei) {
    int tid = blockIdx.x * 256 + threadIdx.x;     // EE/4 threads
    int e0 = tid * 4;
    int r[4], c[4];
    idx4_at(ei, e0, r);
    idx4_at(ei, (long long)EE + e0, c);
    #pragma unroll
    for (int i = 0; i < 4; i++) {
        int pos = atomicAdd(&g_rowpos[r[i]], 1);
        g_col[g_rowstart[r[i]] + pos] = c[i];
    }
}

// ================= K5/K6: SpMM  out = L @ in ================================
// acc = x[r] - dinv[r] * sum_e dinv[c_e] * x[c_e]   (val never materialized)
template <int PASS>
__global__ void spmm_kernel(const float* __restrict__ x) {
    const float* hin  = (PASS == 0) ? x : (const float*)g_H2;
    float*       hout = (PASS == 0) ? g_H2 : g_H3;
    int warp = threadIdx.x >> 5, lane = threadIdx.x & 31;
    int r = blockIdx.x * 8 + warp;
    const float2* in2 = (const float2*)hin;
    float2 base0 = in2[r * 32 + lane];
    float2 acc; acc.x = 0.f; acc.y = 0.f;
    int s = g_rowstart[r], e = g_rowstart[r + 1];
    for (int base = s; base < e; base += 32) {
        int j = base + lane;
        int c = 0; float w = 0.f;
        if (j < e) { c = g_col[j]; w = g_dinv[c]; }
        int m = min(32, e - base);
        for (int q = 0; q < m; q++) {
            int cc = __shfl_sync(0xffffffffu, c, q);
            float ww = __shfl_sync(0xffffffffu, w, q);
            float2 xv = in2[cc * 32 + lane];
            acc.x += ww * xv.x;
            acc.y += ww * xv.y;
        }
    }
    float dr = g_dinv[r];
    base0.x -= dr * acc.x;
    base0.y -= dr * acc.y;
    ((float2*)hout)[r * 32 + lane] = base0;
}

// ================= K7: masked GEMM + BN1-stats epilogue =====================
// BM=64 BN=64 BK=16, 256 threads, 4x4 microtile.
__global__ void gemm_kernel(const float* __restrict__ x, const float* __restrict__ bias) {
    __shared__ __align__(16) float As[16][68];
    __shared__ __align__(16) float Bs[16][68];
    int bx = blockIdx.x, by = blockIdx.y;
    int t = threadIdx.x;
    int kmax = 64 * (bx + 1);
    int tx = t & 15, ty = t >> 4;
    int row0 = by * 64;
    float acc[4][4];
    #pragma unroll
    for (int i = 0; i < 4; i++)
        #pragma unroll
        for (int j = 0; j < 4; j++) acc[i][j] = 0.f;

    int ar = t >> 2, ak4 = t & 3;
    int bo = t & 63, bk = t >> 6;

    for (int k0 = 0; k0 < kmax; k0 += 16) {
        const float* A = (k0 < 64) ? x : (k0 < 128) ? (const float*)g_H2 : (const float*)g_H3;
        int kl = k0 & 63;
        float4 av = *(const float4*)&A[(row0 + ar) * 64 + kl + ak4 * 4];
        As[ak4 * 4 + 0][ar] = av.x;
        As[ak4 * 4 + 1][ar] = av.y;
        As[ak4 * 4 + 2][ar] = av.z;
        As[ak4 * 4 + 3][ar] = av.w;
        #pragma unroll
        for (int i = 0; i < 4; i++) {
            int kk = bk * 4 + i;
            Bs[kk][bo] = g_Wmt[(k0 + kk) * DK + bx * 64 + bo];
        }
        __syncthreads();
        #pragma unroll
        for (int kk = 0; kk < 16; kk++) {
            float4 a = *(float4*)&As[kk][ty * 4];
            float4 bb = *(float4*)&Bs[kk][tx * 4];
            acc[0][0] += a.x * bb.x; acc[0][1] += a.x * bb.y; acc[0][2] += a.x * bb.z; acc[0][3] += a.x * bb.w;
            acc[1][0] += a.y * bb.x; acc[1][1] += a.y * bb.y; acc[1][2] += a.y * bb.z; acc[1][3] += a.y * bb.w;
            acc[2][0] += a.z * bb.x; acc[2][1] += a.z * bb.y; acc[2][2] += a.z * bb.z; acc[2][3] += a.z * bb.w;
            acc[3][0] += a.w * bb.x; acc[3][1] += a.w * bb.y; acc[3][2] += a.w * bb.z; acc[3][3] += a.w * bb.w;
        }
        __syncthreads();
    }
    float4 bv = *(const float4*)&bias[bx * 64 + tx * 4];
    float bj[4] = {bv.x, bv.y, bv.z, bv.w};
    float s[4] = {0.f, 0.f, 0.f, 0.f}, ssq[4] = {0.f, 0.f, 0.f, 0.f};
    #pragma unroll
    for (int i = 0; i < 4; i++) {
        int r = row0 + ty * 4 + i;
        float* dst = &g_H[r * DK + bx * 64 + tx * 4];
        #pragma unroll
        for (int j = 0; j < 4; j++) {
            float val = acc[i][j] + bj[j];
            dst[j] = val;
            s[j] += val;
            ssq[j] += val * val;
        }
    }
    // column reduce across ty (16 groups) via shared, then atomics (spread)
    #pragma unroll
    for (int j = 0; j < 4; j++) { As[ty][tx * 4 + j] = s[j]; Bs[ty][tx * 4 + j] = ssq[j]; }
    __syncthreads();
    if (t < 64) {
        float a = 0.f, b2 = 0.f;
        #pragma unroll
        for (int i = 0; i < 16; i++) { a += As[i][t]; b2 += Bs[i][t]; }
        atomicAdd(&g_csum[bx * 64 + t], a);
        atomicAdd(&g_csumsq[bx * 64 + t], b2);
    }
}

// ================= K8: segmented pool (batch sorted), column-split ==========
// grid (GG, 2), block 96. BN1 inline; writes avg/sum/max thirds of g_Hg.
__global__ void pool_kernel(const float* __restrict__ gamma, const float* __restrict__ beta) {
    int g = blockIdx.x;
    int c = blockIdx.y * 96 + threadIdx.x;
    float m = g_csum[c] * (1.f / NN);
    float var = g_csumsq[c] * (1.f / NN) - m * m;
    float rs = rsqrtf(var + 1e-5f);
    float ga = gamma[c];
    float a = ga * rs, d = beta[c] - ga * m * rs;

    int s = g_gstart[g];
    float sum = 0.f, mx = NEG_HUGE, cnt = 0.f;
    if (s != NN) {
        int e = NN;
        for (int gg = g + 1; gg < GG; gg++) {
            int st = g_gstart[gg];
            if (st != NN) { e = st; break; }
        }
        int r = s;
        for (; r + 4 <= e; r += 4) {
            float h0 = g_H[(r + 0) * DK + c];
            float h1 = g_H[(r + 1) * DK + c];
            float h2 = g_H[(r + 2) * DK + c];
            float h3 = g_H[(r + 3) * DK + c];
            float v0 = a * h0 + d, v1 = a * h1 + d, v2 = a * h2 + d, v3 = a * h3 + d;
            sum += (v0 + v1) + (v2 + v3);
            mx = fmaxf(mx, fmaxf(fmaxf(v0, v1), fmaxf(v2, v3)));
        }
        for (; r < e; r++) {
            float v = a * g_H[r * DK + c] + d;
            sum += v; mx = fmaxf(mx, v);
        }
        cnt = (float)(e - s);
    }
    g_Hg[g * 576 + c]          = sum / fmaxf(cnt, 1.f);
    g_Hg[g * 576 + DK + c]     = sum;
    g_Hg[g * 576 + 2 * DK + c] = mx;
}

// ================= K9: funnel head (bn2 + f1 + f2 + f3) =====================
// grid 16 blocks x 4 graphs each, block 384: weight traffic cut 4x vs 64 blocks.
__global__ void funnel_kernel(const float* __restrict__ g2, const float* __restrict__ be2,
                              const float* __restrict__ b1, const float* __restrict__ b2,
                              const float* __restrict__ w3, const float* __restrict__ b3,
                              float* __restrict__ out) {
    __shared__ float xs[4][576];
    __shared__ float o1s[4][384];
    __shared__ float o2s[4][192];
    int g0 = blockIdx.x * 4, t = threadIdx.x;

    for (int c = t; c < 576; c += 384) {
        float s = 0.f, ss = 0.f;
        for (int gg = 0; gg < GG; gg++) {
            float v = g_Hg[gg * 576 + c];
            s += v; ss += v * v;
        }
        float m = s * (1.f / GG);
        float var = ss * (1.f / GG) - m * m;
        float rs = rsqrtf(var + 1e-5f);
        float ga = g2[c], be = be2[c];
        #pragma unroll
        for (int i = 0; i < 4; i++)
            xs[i][c] = ga * (g_Hg[(g0 + i) * 576 + c] - m) * rs + be;
    }
    __syncthreads();

    {
        float a0 = 0.f, a1 = 0.f, a2 = 0.f, a3 = 0.f;
        for (int k = 0; k < 576; k++) {
            float w = g_w1t[k * 384 + t];
            a0 += xs[0][k] * w; a1 += xs[1][k] * w; a2 += xs[2][k] * w; a3 += xs[3][k] * w;
        }
        float bb = b1[t];
        o1s[0][t] = fmaxf(a0 + bb, 0.f);
        o1s[1][t] = fmaxf(a1 + bb, 0.f);
        o1s[2][t] = fmaxf(a2 + bb, 0.f);
        o1s[3][t] = fmaxf(a3 + bb, 0.f);
    }
    __syncthreads();

    {
        int o = t % 192, pair = t / 192;     // threads split: 2 graphs each half
        float a0 = 0.f, a1 = 0.f;
        for (int k = 0; k < 384; k++) {
            float w = g_w2t[k * 192 + o];
            a0 += o1s[pair * 2 + 0][k] * w;
            a1 += o1s[pair * 2 + 1][k] * w;
        }
        float bb = b2[o];
        o2s[pair * 2 + 0][o] = fmaxf(a0 + bb, 0.f);
        o2s[pair * 2 + 1][o] = fmaxf(a1 + bb, 0.f);
    }
    __syncthreads();

    {
        int wid = t >> 5, lane = t & 31;     // warps 0..3 -> graphs g0..g0+3
        if (wid < 4) {
            float l = -INFINITY;
            if (lane < NC) {
                float a = b3[lane];
                for (int k = 0; k < 192; k++) a += o2s[wid][k] * w3[lane * 192 + k];
                l = a;
            }
            float m = l;
            #pragma unroll
            for (int o = 16; o; o >>= 1) m = fmaxf(m, __shfl_xor_sync(0xffffffffu, m, o));
            float e = (lane < NC) ? expf(l - m) : 0.f;
            float s = e;
            #pragma unroll
            for (int o = 16; o; o >>= 1) s += __shfl_xor_sync(0xffffffffu, s, o);
            if (lane < NC) out[(g0 + wid) * NC + lane] = l - m - logf(s);
        }
    }
}

// ---------------- launch ----------------
extern "C" void kernel_launch(void* const* d_in, const int* in_sizes, int n_in,
                              void* d_out, int out_size) {
    const float* x     = (const float*)d_in[0];
    const void*  ei    = d_in[1];
    const void*  batch = d_in[2];
    const float* W     = (const float*)d_in[3];
    const float* b     = (const float*)d_in[4];
    const float* u     = (const float*)d_in[5];
    const float* g1    = (const float*)d_in[6];
    const float* be1   = (const float*)d_in[7];
    const float* g2    = (const float*)d_in[8];
    const float* be2   = (const float*)d_in[9];
    const float* w1    = (const float*)d_in[10];
    const float* b1    = (const float*)d_in[11];
    const float* w2    = (const float*)d_in[12];
    const float* b2    = (const float*)d_in[13];
    const float* w3    = (const float*)d_in[14];
    const float* b3    = (const float*)d_in[15];
    float* out = (float*)d_out;

    prep_kernel<<<TW_TOTAL / 256, 256>>>(ei, W, u, w1, w2);   // 1152 blocks
    deg_kernel<<<EE / 1024, 256>>>(ei, batch);                // 4 edges/thread
    scan_kernel<<<1, 1024>>>();
    csr_kernel<<<EE / 1024, 256>>>(ei);                       // 4 edges/thread
    spmm_kernel<0><<<NN / 8, 256>>>(x);
    spmm_kernel<1><<<NN / 8, 256>>>(x);
    {
        dim3 grid(3, NN / 64);
        gemm_kernel<<<grid, 256>>>(x, b);
    }
    {
        dim3 pgrid(GG, 2);
        pool_kernel<<<pgrid, 96>>>(g1, be1);
    }
    funnel_kernel<<<16, 384>>>(g2, be2, b1, b2, w3, b3, out);
}

// round 15
// speedup vs baseline: 1.1485x; 1.1485x over previous
#include <cuda_runtime.h>
#include <cuda_bf16.h>
#include <math.h>

#define NN 8192
#define EE 262144
#define INC 64
#define DK 192      // IN_C*K = OUT_C*K
#define GG 64
#define NC 10
#define NEG_HUGE (-3.402823466e38f)

// ---------------- static scratch ----------------
__device__ int   g_is64;                  // 1 if index tensors are int64, 0 if int32
__device__ int   g_degi[NN];
__device__ float g_dinv[NN];
__device__ int   g_rowstart[NN + 1];
__device__ int   g_rowpos[NN];
__device__ int   g_gstart[GG];            // first row of each graph (NN if empty)
__device__ __align__(16) int   g_col[EE];
__device__ __align__(16) float g_val[EE];
__device__ __align__(16) float g_H2[NN * INC];
__device__ __align__(16) float g_H3[NN * INC];
__device__ __align__(16) float g_H[NN * DK];
__device__ __align__(16) float g_Wmt[DK * DK];   // transposed masked/scaled weight [k][o]
__device__ float g_csum[DK], g_csumsq[DK];
__device__ __align__(16) float g_Hg[GG * 576];
__device__ __align__(16) float g_w1t[576 * 384];
__device__ __align__(16) float g_w2t[384 * 192];

// index accessor: handles both int32 and int64 on-disk layouts
__device__ __forceinline__ int idx_at(const void* p, long long i) {
    if (g_is64) return (int)(((const long long*)p)[i]);
    return ((const int*)p)[i];
}

// load 4 consecutive indices starting at 4-aligned element e0
__device__ __forceinline__ void idx4_at(const void* p, long long e0, int* o) {
    if (g_is64) {
        const longlong2* q = (const longlong2*)((const long long*)p + e0);
        longlong2 a = q[0], b = q[1];
        o[0] = (int)a.x; o[1] = (int)a.y; o[2] = (int)b.x; o[3] = (int)b.y;
    } else {
        int4 a = *(const int4*)((const int*)p + e0);
        o[0] = a.x; o[1] = a.y; o[2] = a.z; o[3] = a.w;
    }
}

// ================= K1: prep =================
// blocks 0..47: zero scratch; all blocks: strided w1/w2 transpose;
// block 48: dtype detect; block 49: spectral-norm + mask -> g_Wmt.
#define TW_TOTAL (384 * 576 + 192 * 384)   // 294912
__global__ void prep_kernel(const void* __restrict__ ei,
                            const float* __restrict__ W, const float* __restrict__ u,
                            const float* __restrict__ w1, const float* __restrict__ w2) {
    __shared__ float v[DK];
    __shared__ float red[256];
    __shared__ float s_nrm, s_inv;
    int blk = blockIdx.x, t = threadIdx.x;

    for (int idx = blk * 256 + t; idx < TW_TOTAL; idx += gridDim.x * 256) {
        if (idx < 384 * 576) {
            int o = idx / 576, k = idx - o * 576;
            g_w1t[k * 384 + o] = w1[idx];
        } else {
            int j = idx - 384 * 576;
            int o = j / 384, k = j - o * 384;
            g_w2t[k * 192 + o] = w2[j];
        }
    }

    if (blk < 48) {
        int i = blk * 256 + t;
        if (i < NN) { g_degi[i] = 0; g_rowpos[i] = 0; }
        if (i < DK) { g_csum[i] = 0.f; g_csumsq[i] = 0.f; }
        if (i < GG) g_gstart[i] = NN;
    } else if (blk == 48) {
        if (t == 0) {
            const int* p = (const int*)ei;
            int zeros = 0;
            for (int i = 0; i < 64; i++)
                if (p[2 * i + 1] == 0) zeros++;
            g_is64 = (zeros >= 48) ? 1 : 0;
        }
    } else if (blk == 49) {
        // ---- wprep: v = W^T u ; normalize ; sigma = u.(W v) ; masked scale ----
        if (t < DK) {
            float a = 0.f;
            for (int i = 0; i < DK; i++) a += W[i * DK + t] * u[i];
            v[t] = a;
        }
        __syncthreads();
        red[t] = (t < DK) ? v[t] * v[t] : 0.f;
        __syncthreads();
        for (int s = 128; s > 0; s >>= 1) { if (t < s) red[t] += red[t + s]; __syncthreads(); }
        if (t == 0) s_nrm = sqrtf(red[0]) + 1e-12f;
        __syncthreads();
        if (t < DK) v[t] /= s_nrm;
        __syncthreads();
        float p = 0.f;
        if (t < DK) {
            float a = 0.f;
            for (int j = 0; j < DK; j++) a += W[t * DK + j] * v[j];
            p = a * u[t];
        }
        red[t] = p;
        __syncthreads();
        for (int s = 128; s > 0; s >>= 1) { if (t < s) red[t] += red[t + s]; __syncthreads(); }
        if (t == 0) s_inv = 1.0f / red[0];
        __syncthreads();
        for (int idx = t; idx < DK * DK; idx += 256) {
            int o = idx / DK, k = idx - o * DK;
            float mv = (k < 64 * ((o >> 6) + 1)) ? W[idx] * s_inv : 0.f;
            g_Wmt[k * DK + o] = mv;
        }
    }
}

// ================= K2: degrees + graph boundaries (4 edges/thread) =========
__global__ void deg_kernel(const void* __restrict__ ei, const void* __restrict__ batch) {
    int tid = blockIdx.x * 256 + threadIdx.x;     // EE/4 threads
    int e0 = tid * 4;
    int r[4];
    idx4_at(ei, e0, r);
    #pragma unroll
    for (int i = 0; i < 4; i++) atomicAdd(&g_degi[r[i]], 1);
    if (tid < NN / 4) {
        int n0 = tid * 4;
        int b[4];
        idx4_at(batch, n0, b);
        int prev = (n0 == 0) ? -1 : idx_at(batch, n0 - 1);
        #pragma unroll
        for (int i = 0; i < 4; i++) {
            if (b[i] != prev) g_gstart[b[i]] = n0 + i;
            prev = b[i];
        }
    }
}

// ================= K3: scan + dinv (1 block, 1024 threads) =================
__global__ void scan_kernel() {
    __shared__ int sh[1024];
    int t = threadIdx.x;
    int base = t * 8;
    int loc[8];
    int s = 0;
    #pragma unroll
    for (int i = 0; i < 8; i++) {
        int d = g_degi[base + i];
        loc[i] = s; s += d;
        g_dinv[base + i] = (d > 0) ? rsqrtf((float)d) : 0.f;
    }
    sh[t] = s;
    __syncthreads();
    for (int off = 1; off < 1024; off <<= 1) {
        int v = (t >= off) ? sh[t - off] : 0;
        __syncthreads();
        sh[t] += v;
        __syncthreads();
    }
    int offset = (t > 0) ? sh[t - 1] : 0;
    #pragma unroll
    for (int i = 0; i < 8; i++) g_rowstart[base + i] = offset + loc[i];
    if (t == 1023) g_rowstart[NN] = sh[1023];
}

// ================= K4: CSR build (4 edges/thread, val materialized) =========
__global__ void csr_kernel(const void* __restrict__ ei) {
    int tid = blockIdx.x * 256 + threadIdx.x;     // EE/4 threads
    int e0 = tid * 4;
    int r[4], c[4];
    idx4_at(ei, e0, r);
    idx4_at(ei, (long long)EE + e0, c);
    #pragma unroll
    for (int i = 0; i < 4; i++) {
        int pos = atomicAdd(&g_rowpos[r[i]], 1);
        int at = g_rowstart[r[i]] + pos;
        g_col[at] = c[i];
        g_val[at] = -g_dinv[r[i]] * g_dinv[c[i]];
    }
}

// ================= K5/K6: SpMM  out = L @ in ================================
template <int PASS>
__global__ void spmm_kernel(const float* __restrict__ x) {
    const float* hin  = (PASS == 0) ? x : (const float*)g_H2;
    float*       hout = (PASS == 0) ? g_H2 : g_H3;
    int warp = threadIdx.x >> 5, lane = threadIdx.x & 31;
    int r = blockIdx.x * 8 + warp;
    const float2* in2 = (const float2*)hin;
    float2 acc = in2[r * 32 + lane];
    int s = g_rowstart[r], e = g_rowstart[r + 1];
    for (int base = s; base < e; base += 32) {
        int j = base + lane;
        int c = 0; float v = 0.f;
        if (j < e) { c = g_col[j]; v = g_val[j]; }
        int m = min(32, e - base);
        for (int q = 0; q < m; q++) {
            int cc = __shfl_sync(0xffffffffu, c, q);
            float vv = __shfl_sync(0xffffffffu, v, q);
            float2 xv = in2[cc * 32 + lane];
            acc.x += vv * xv.x;
            acc.y += vv * xv.y;
        }
    }
    ((float2*)hout)[r * 32 + lane] = acc;
}

// ================= K7: masked GEMM + BN1-stats epilogue =====================
// BM=64 BN=64 BK=16, 256 threads, 4x4 microtile.
__global__ void gemm_kernel(const float* __restrict__ x, const float* __restrict__ bias) {
    __shared__ __align__(16) float As[16][68];
    __shared__ __align__(16) float Bs[16][68];
    int bx = blockIdx.x, by = blockIdx.y;
    int t = threadIdx.x;
    int kmax = 64 * (bx + 1);
    int tx = t & 15, ty = t >> 4;
    int row0 = by * 64;
    float acc[4][4];
    #pragma unroll
    for (int i = 0; i < 4; i++)
        #pragma unroll
        for (int j = 0; j < 4; j++) acc[i][j] = 0.f;

    int ar = t >> 2, ak4 = t & 3;
    int bo = t & 63, bk = t >> 6;

    for (int k0 = 0; k0 < kmax; k0 += 16) {
        const float* A = (k0 < 64) ? x : (k0 < 128) ? (const float*)g_H2 : (const float*)g_H3;
        int kl = k0 & 63;
        float4 av = *(const float4*)&A[(row0 + ar) * 64 + kl + ak4 * 4];
        As[ak4 * 4 + 0][ar] = av.x;
        As[ak4 * 4 + 1][ar] = av.y;
        As[ak4 * 4 + 2][ar] = av.z;
        As[ak4 * 4 + 3][ar] = av.w;
        #pragma unroll
        for (int i = 0; i < 4; i++) {
            int kk = bk * 4 + i;
            Bs[kk][bo] = g_Wmt[(k0 + kk) * DK + bx * 64 + bo];
        }
        __syncthreads();
        #pragma unroll
        for (int kk = 0; kk < 16; kk++) {
            float4 a = *(float4*)&As[kk][ty * 4];
            float4 bb = *(float4*)&Bs[kk][tx * 4];
            acc[0][0] += a.x * bb.x; acc[0][1] += a.x * bb.y; acc[0][2] += a.x * bb.z; acc[0][3] += a.x * bb.w;
            acc[1][0] += a.y * bb.x; acc[1][1] += a.y * bb.y; acc[1][2] += a.y * bb.z; acc[1][3] += a.y * bb.w;
            acc[2][0] += a.z * bb.x; acc[2][1] += a.z * bb.y; acc[2][2] += a.z * bb.z; acc[2][3] += a.z * bb.w;
            acc[3][0] += a.w * bb.x; acc[3][1] += a.w * bb.y; acc[3][2] += a.w * bb.z; acc[3][3] += a.w * bb.w;
        }
        __syncthreads();
    }
    float4 bv = *(const float4*)&bias[bx * 64 + tx * 4];
    float bj[4] = {bv.x, bv.y, bv.z, bv.w};
    float s[4] = {0.f, 0.f, 0.f, 0.f}, ssq[4] = {0.f, 0.f, 0.f, 0.f};
    #pragma unroll
    for (int i = 0; i < 4; i++) {
        int r = row0 + ty * 4 + i;
        float* dst = &g_H[r * DK + bx * 64 + tx * 4];
        #pragma unroll
        for (int j = 0; j < 4; j++) {
            float val = acc[i][j] + bj[j];
            dst[j] = val;
            s[j] += val;
            ssq[j] += val * val;
        }
    }
    // column reduce across ty (16 groups) via shared, then atomics (spread)
    #pragma unroll
    for (int j = 0; j < 4; j++) { As[ty][tx * 4 + j] = s[j]; Bs[ty][tx * 4 + j] = ssq[j]; }
    __syncthreads();
    if (t < 64) {
        float a = 0.f, b2 = 0.f;
        #pragma unroll
        for (int i = 0; i < 16; i++) { a += As[i][t]; b2 += Bs[i][t]; }
        atomicAdd(&g_csum[bx * 64 + t], a);
        atomicAdd(&g_csumsq[bx * 64 + t], b2);
    }
}

// ================= K8: segmented pool (batch is sorted) =====================
// grid GG, block DK. BN1 applied inline; writes avg/sum/max thirds of g_Hg.
__global__ void pool_kernel(const float* __restrict__ gamma, const float* __restrict__ beta) {
    int g = blockIdx.x, c = threadIdx.x;
    float m = g_csum[c] * (1.f / NN);
    float var = g_csumsq[c] * (1.f / NN) - m * m;
    float rs = rsqrtf(var + 1e-5f);
    float ga = gamma[c];
    float a = ga * rs, d = beta[c] - ga * m * rs;

    int s = g_gstart[g];
    float sum = 0.f, mx = NEG_HUGE, cnt = 0.f;
    if (s != NN) {
        int e = NN;
        for (int gg = g + 1; gg < GG; gg++) {
            int st = g_gstart[gg];
            if (st != NN) { e = st; break; }
        }
        int r = s;
        for (; r + 4 <= e; r += 4) {
            float h0 = g_H[(r + 0) * DK + c];
            float h1 = g_H[(r + 1) * DK + c];
            float h2 = g_H[(r + 2) * DK + c];
            float h3 = g_H[(r + 3) * DK + c];
            float v0 = a * h0 + d, v1 = a * h1 + d, v2 = a * h2 + d, v3 = a * h3 + d;
            sum += (v0 + v1) + (v2 + v3);
            mx = fmaxf(mx, fmaxf(fmaxf(v0, v1), fmaxf(v2, v3)));
        }
        for (; r < e; r++) {
            float v = a * g_H[r * DK + c] + d;
            sum += v; mx = fmaxf(mx, v);
        }
        cnt = (float)(e - s);
    }
    g_Hg[g * 576 + c]          = sum / fmaxf(cnt, 1.f);
    g_Hg[g * 576 + DK + c]     = sum;
    g_Hg[g * 576 + 2 * DK + c] = mx;
}

// ================= K9: funnel head (bn2 + f1 + f2 + f3) =====================
// grid GG, block 384. bn2 stats recomputed per block (cheap, L2-resident).
__global__ void funnel_kernel(const float* __restrict__ g2, const float* __restrict__ be2,
                              const float* __restrict__ b1, const float* __restrict__ b2,
                              const float* __restrict__ w3, const float* __restrict__ b3,
                              float* __restrict__ out) {
    __shared__ float xs[576];
    __shared__ float o1s[384];
    __shared__ float o2s[192];
    int g = blockIdx.x, t = threadIdx.x;

    for (int c = t; c < 576; c += 384) {
        float s = 0.f, ss = 0.f;
        for (int gg = 0; gg < GG; gg++) {
            float v = g_Hg[gg * 576 + c];
            s += v; ss += v * v;
        }
        float m = s * (1.f / GG);
        float var = ss * (1.f / GG) - m * m;
        float rs = rsqrtf(var + 1e-5f);
        xs[c] = g2[c] * (g_Hg[g * 576 + c] - m) * rs + be2[c];
    }
    __syncthreads();

    {
        float a = b1[t];
        for (int k = 0; k < 576; k++) a += xs[k] * g_w1t[k * 384 + t];
        o1s[t] = fmaxf(a, 0.f);
    }
    __syncthreads();

    if (t < 192) {
        float a = b2[t];
        for (int k = 0; k < 384; k++) a += o1s[k] * g_w2t[k * 192 + t];
        o2s[t] = fmaxf(a, 0.f);
    }
    __syncthreads();

    if (t < 32) {
        int lane = t;
        float l = -INFINITY;
        if (lane < NC) {
            float a = b3[lane];
            for (int k = 0; k < 192; k++) a += o2s[k] * w3[lane * 192 + k];
            l = a;
        }
        float m = l;
        #pragma unroll
        for (int o = 16; o; o >>= 1) m = fmaxf(m, __shfl_xor_sync(0xffffffffu, m, o));
        float e = (lane < NC) ? expf(l - m) : 0.f;
        float s = e;
        #pragma unroll
        for (int o = 16; o; o >>= 1) s += __shfl_xor_sync(0xffffffffu, s, o);
        if (lane < NC) out[g * NC + lane] = l - m - logf(s);
    }
}

// ---------------- launch ----------------
extern "C" void kernel_launch(void* const* d_in, const int* in_sizes, int n_in,
                              void* d_out, int out_size) {
    const float* x     = (const float*)d_in[0];
    const void*  ei    = d_in[1];
    const void*  batch = d_in[2];
    const float* W     = (const float*)d_in[3];
    const float* b     = (const float*)d_in[4];
    const float* u     = (const float*)d_in[5];
    const float* g1    = (const float*)d_in[6];
    const float* be1   = (const float*)d_in[7];
    const float* g2    = (const float*)d_in[8];
    const float* be2   = (const float*)d_in[9];
    const float* w1    = (const float*)d_in[10];
    const float* b1    = (const float*)d_in[11];
    const float* w2    = (const float*)d_in[12];
    const float* b2    = (const float*)d_in[13];
    const float* w3    = (const float*)d_in[14];
    const float* b3    = (const float*)d_in[15];
    float* out = (float*)d_out;

    prep_kernel<<<TW_TOTAL / 256, 256>>>(ei, W, u, w1, w2);   // 1152 blocks
    deg_kernel<<<EE / 1024, 256>>>(ei, batch);                // 4 edges/thread
    scan_kernel<<<1, 1024>>>();
    csr_kernel<<<EE / 1024, 256>>>(ei);                       // 4 edges/thread
    spmm_kernel<0><<<NN / 8, 256>>>(x);
    spmm_kernel<1><<<NN / 8, 256>>>(x);
    {
        dim3 grid(3, NN / 64);
        gemm_kernel<<<grid, 256>>>(x, b);
    }
    pool_kernel<<<GG, DK>>>(g1, be1);
    funnel_kernel<<<GG, 384>>>(g2, be2, b1, b2, w3, b3, out);
}

// round 16
// speedup vs baseline: 1.1950x; 1.0405x over previous
#include <cuda_runtime.h>
#include <cuda_bf16.h>
#include <math.h>

#define NN 8192
#define EE 262144
#define INC 64
#define DK 192      // IN_C*K = OUT_C*K
#define GG 64
#define NC 10
#define NEG_HUGE (-3.402823466e38f)

// ---------------- static scratch ----------------
__device__ int   g_is64;                  // 1 if index tensors are int64, 0 if int32
__device__ int   g_degi[NN];
__device__ float g_dinv[NN];
__device__ int   g_rowstart[NN + 1];
__device__ int   g_gstart[GG];            // first row of each graph (NN if empty)
__device__ __align__(16) int   g_pos[EE]; // edge's slot within its row (from deg pass)
__device__ __align__(16) int   g_col[EE];
__device__ __align__(16) float g_val[EE];
__device__ __align__(16) float g_H2[NN * INC];
__device__ __align__(16) float g_H3[NN * INC];
__device__ __align__(16) float g_H[NN * DK];
__device__ __align__(16) float g_Wmt[DK * DK];   // transposed masked/scaled weight [k][o]
__device__ float g_csum[DK], g_csumsq[DK];
__device__ __align__(16) float g_Hg[GG * 576];
__device__ __align__(16) float g_w1t[576 * 384];
__device__ __align__(16) float g_w2t[384 * 192];

// index accessor: handles both int32 and int64 on-disk layouts
__device__ __forceinline__ int idx_at(const void* p, long long i) {
    if (g_is64) return (int)(((const long long*)p)[i]);
    return ((const int*)p)[i];
}

// load 4 consecutive indices starting at 4-aligned element e0
__device__ __forceinline__ void idx4_at(const void* p, long long e0, int* o) {
    if (g_is64) {
        const longlong2* q = (const longlong2*)((const long long*)p + e0);
        longlong2 a = q[0], b = q[1];
        o[0] = (int)a.x; o[1] = (int)a.y; o[2] = (int)b.x; o[3] = (int)b.y;
    } else {
        int4 a = *(const int4*)((const int*)p + e0);
        o[0] = a.x; o[1] = a.y; o[2] = a.z; o[3] = a.w;
    }
}

// ================= K1: prep =================
// blocks 0..47: zero scratch; all blocks: strided w1/w2 transpose;
// block 48: dtype detect; block 49: spectral-norm + mask -> g_Wmt.
#define TW_TOTAL (384 * 576 + 192 * 384)   // 294912
__global__ void prep_kernel(const void* __restrict__ ei,
                            const float* __restrict__ W, const float* __restrict__ u,
                            const float* __restrict__ w1, const float* __restrict__ w2) {
    __shared__ float v[DK];
    __shared__ float red[256];
    __shared__ float s_nrm, s_inv;
    int blk = blockIdx.x, t = threadIdx.x;

    for (int idx = blk * 256 + t; idx < TW_TOTAL; idx += gridDim.x * 256) {
        if (idx < 384 * 576) {
            int o = idx / 576, k = idx - o * 576;
            g_w1t[k * 384 + o] = w1[idx];
        } else {
            int j = idx - 384 * 576;
            int o = j / 384, k = j - o * 384;
            g_w2t[k * 192 + o] = w2[j];
        }
    }

    if (blk < 48) {
        int i = blk * 256 + t;
        if (i < NN) g_degi[i] = 0;
        if (i < DK) { g_csum[i] = 0.f; g_csumsq[i] = 0.f; }
        if (i < GG) g_gstart[i] = NN;
    } else if (blk == 48) {
        if (t == 0) {
            const int* p = (const int*)ei;
            int zeros = 0;
            for (int i = 0; i < 64; i++)
                if (p[2 * i + 1] == 0) zeros++;
            g_is64 = (zeros >= 48) ? 1 : 0;
        }
    } else if (blk == 49) {
        // ---- wprep: v = W^T u ; normalize ; sigma = u.(W v) ; masked scale ----
        if (t < DK) {
            float a = 0.f;
            for (int i = 0; i < DK; i++) a += W[i * DK + t] * u[i];
            v[t] = a;
        }
        __syncthreads();
        red[t] = (t < DK) ? v[t] * v[t] : 0.f;
        __syncthreads();
        for (int s = 128; s > 0; s >>= 1) { if (t < s) red[t] += red[t + s]; __syncthreads(); }
        if (t == 0) s_nrm = sqrtf(red[0]) + 1e-12f;
        __syncthreads();
        if (t < DK) v[t] /= s_nrm;
        __syncthreads();
        float p = 0.f;
        if (t < DK) {
            float a = 0.f;
            for (int j = 0; j < DK; j++) a += W[t * DK + j] * v[j];
            p = a * u[t];
        }
        red[t] = p;
        __syncthreads();
        for (int s = 128; s > 0; s >>= 1) { if (t < s) red[t] += red[t + s]; __syncthreads(); }
        if (t == 0) s_inv = 1.0f / red[0];
        __syncthreads();
        for (int idx = t; idx < DK * DK; idx += 256) {
            int o = idx / DK, k = idx - o * DK;
            float mv = (k < 64 * ((o >> 6) + 1)) ? W[idx] * s_inv : 0.f;
            g_Wmt[k * DK + o] = mv;
        }
    }
}

// ================= K2: degrees + per-edge slot + graph boundaries ==========
// The deg atomic's return value IS the edge's position within its row; store
// it so the CSR pass needs no second (contended) atomic.
__global__ void deg_kernel(const void* __restrict__ ei, const void* __restrict__ batch) {
    int tid = blockIdx.x * 256 + threadIdx.x;     // EE/4 threads
    int e0 = tid * 4;
    int r[4];
    idx4_at(ei, e0, r);
    int p[4];
    #pragma unroll
    for (int i = 0; i < 4; i++) p[i] = atomicAdd(&g_degi[r[i]], 1);
    *(int4*)&g_pos[e0] = make_int4(p[0], p[1], p[2], p[3]);
    if (tid < NN / 4) {
        int n0 = tid * 4;
        int b[4];
        idx4_at(batch, n0, b);
        int prev = (n0 == 0) ? -1 : idx_at(batch, n0 - 1);
        #pragma unroll
        for (int i = 0; i < 4; i++) {
            if (b[i] != prev) g_gstart[b[i]] = n0 + i;
            prev = b[i];
        }
    }
}

// ================= K3: scan + dinv (1 block, 1024 threads) =================
__global__ void scan_kernel() {
    __shared__ int sh[1024];
    int t = threadIdx.x;
    int base = t * 8;
    int loc[8];
    int s = 0;
    #pragma unroll
    for (int i = 0; i < 8; i++) {
        int d = g_degi[base + i];
        loc[i] = s; s += d;
        g_dinv[base + i] = (d > 0) ? rsqrtf((float)d) : 0.f;
    }
    sh[t] = s;
    __syncthreads();
    for (int off = 1; off < 1024; off <<= 1) {
        int v = (t >= off) ? sh[t - off] : 0;
        __syncthreads();
        sh[t] += v;
        __syncthreads();
    }
    int offset = (t > 0) ? sh[t - 1] : 0;
    #pragma unroll
    for (int i = 0; i < 8; i++) g_rowstart[base + i] = offset + loc[i];
    if (t == 1023) g_rowstart[NN] = sh[1023];
}

// ================= K4: CSR build — atomic-free scatter ======================
__global__ void csr_kernel(const void* __restrict__ ei) {
    int tid = blockIdx.x * 256 + threadIdx.x;     // EE/4 threads
    int e0 = tid * 4;
    int r[4], c[4];
    idx4_at(ei, e0, r);
    idx4_at(ei, (long long)EE + e0, c);
    int4 pv = *(const int4*)&g_pos[e0];
    int p[4] = {pv.x, pv.y, pv.z, pv.w};
    #pragma unroll
    for (int i = 0; i < 4; i++) {
        int at = g_rowstart[r[i]] + p[i];
        g_col[at] = c[i];
        g_val[at] = -g_dinv[r[i]] * g_dinv[c[i]];
    }
}

// ================= K5/K6: SpMM  out = L @ in ================================
template <int PASS>
__global__ void spmm_kernel(const float* __restrict__ x) {
    const float* hin  = (PASS == 0) ? x : (const float*)g_H2;
    float*       hout = (PASS == 0) ? g_H2 : g_H3;
    int warp = threadIdx.x >> 5, lane = threadIdx.x & 31;
    int r = blockIdx.x * 8 + warp;
    const float2* in2 = (const float2*)hin;
    float2 acc = in2[r * 32 + lane];
    int s = g_rowstart[r], e = g_rowstart[r + 1];
    for (int base = s; base < e; base += 32) {
        int j = base + lane;
        int c = 0; float v = 0.f;
        if (j < e) { c = g_col[j]; v = g_val[j]; }
        int m = min(32, e - base);
        for (int q = 0; q < m; q++) {
            int cc = __shfl_sync(0xffffffffu, c, q);
            float vv = __shfl_sync(0xffffffffu, v, q);
            float2 xv = in2[cc * 32 + lane];
            acc.x += vv * xv.x;
            acc.y += vv * xv.y;
        }
    }
    ((float2*)hout)[r * 32 + lane] = acc;
}

// ================= K7: masked GEMM + BN1-stats epilogue =====================
// BM=64 BN=64 BK=16, 256 threads, 4x4 microtile.
__global__ void gemm_kernel(const float* __restrict__ x, const float* __restrict__ bias) {
    __shared__ __align__(16) float As[16][68];
    __shared__ __align__(16) float Bs[16][68];
    int bx = blockIdx.x, by = blockIdx.y;
    int t = threadIdx.x;
    int kmax = 64 * (bx + 1);
    int tx = t & 15, ty = t >> 4;
    int row0 = by * 64;
    float acc[4][4];
    #pragma unroll
    for (int i = 0; i < 4; i++)
        #pragma unroll
        for (int j = 0; j < 4; j++) acc[i][j] = 0.f;

    int ar = t >> 2, ak4 = t & 3;
    int bo = t & 63, bk = t >> 6;

    for (int k0 = 0; k0 < kmax; k0 += 16) {
        const float* A = (k0 < 64) ? x : (k0 < 128) ? (const float*)g_H2 : (const float*)g_H3;
        int kl = k0 & 63;
        float4 av = *(const float4*)&A[(row0 + ar) * 64 + kl + ak4 * 4];
        As[ak4 * 4 + 0][ar] = av.x;
        As[ak4 * 4 + 1][ar] = av.y;
        As[ak4 * 4 + 2][ar] = av.z;
        As[ak4 * 4 + 3][ar] = av.w;
        #pragma unroll
        for (int i = 0; i < 4; i++) {
            int kk = bk * 4 + i;
            Bs[kk][bo] = g_Wmt[(k0 + kk) * DK + bx * 64 + bo];
        }
        __syncthreads();
        #pragma unroll
        for (int kk = 0; kk < 16; kk++) {
            float4 a = *(float4*)&As[kk][ty * 4];
            float4 bb = *(float4*)&Bs[kk][tx * 4];
            acc[0][0] += a.x * bb.x; acc[0][1] += a.x * bb.y; acc[0][2] += a.x * bb.z; acc[0][3] += a.x * bb.w;
            acc[1][0] += a.y * bb.x; acc[1][1] += a.y * bb.y; acc[1][2] += a.y * bb.z; acc[1][3] += a.y * bb.w;
            acc[2][0] += a.z * bb.x; acc[2][1] += a.z * bb.y; acc[2][2] += a.z * bb.z; acc[2][3] += a.z * bb.w;
            acc[3][0] += a.w * bb.x; acc[3][1] += a.w * bb.y; acc[3][2] += a.w * bb.z; acc[3][3] += a.w * bb.w;
        }
        __syncthreads();
    }
    float4 bv = *(const float4*)&bias[bx * 64 + tx * 4];
    float bj[4] = {bv.x, bv.y, bv.z, bv.w};
    float s[4] = {0.f, 0.f, 0.f, 0.f}, ssq[4] = {0.f, 0.f, 0.f, 0.f};
    #pragma unroll
    for (int i = 0; i < 4; i++) {
        int r = row0 + ty * 4 + i;
        float* dst = &g_H[r * DK + bx * 64 + tx * 4];
        #pragma unroll
        for (int j = 0; j < 4; j++) {
            float val = acc[i][j] + bj[j];
            dst[j] = val;
            s[j] += val;
            ssq[j] += val * val;
        }
    }
    // column reduce across ty (16 groups) via shared, then atomics (spread)
    #pragma unroll
    for (int j = 0; j < 4; j++) { As[ty][tx * 4 + j] = s[j]; Bs[ty][tx * 4 + j] = ssq[j]; }
    __syncthreads();
    if (t < 64) {
        float a = 0.f, b2 = 0.f;
        #pragma unroll
        for (int i = 0; i < 16; i++) { a += As[i][t]; b2 += Bs[i][t]; }
        atomicAdd(&g_csum[bx * 64 + t], a);
        atomicAdd(&g_csumsq[bx * 64 + t], b2);
    }
}

// ================= K8: segmented pool (batch is sorted) =====================
// grid GG, block DK. BN1 applied inline; writes avg/sum/max thirds of g_Hg.
__global__ void pool_kernel(const float* __restrict__ gamma, const float* __restrict__ beta) {
    int g = blockIdx.x, c = threadIdx.x;
    float m = g_csum[c] * (1.f / NN);
    float var = g_csumsq[c] * (1.f / NN) - m * m;
    float rs = rsqrtf(var + 1e-5f);
    float ga = gamma[c];
    float a = ga * rs, d = beta[c] - ga * m * rs;

    int s = g_gstart[g];
    float sum = 0.f, mx = NEG_HUGE, cnt = 0.f;
    if (s != NN) {
        int e = NN;
        for (int gg = g + 1; gg < GG; gg++) {
            int st = g_gstart[gg];
            if (st != NN) { e = st; break; }
        }
        int r = s;
        for (; r + 4 <= e; r += 4) {
            float h0 = g_H[(r + 0) * DK + c];
            float h1 = g_H[(r + 1) * DK + c];
            float h2 = g_H[(r + 2) * DK + c];
            float h3 = g_H[(r + 3) * DK + c];
            float v0 = a * h0 + d, v1 = a * h1 + d, v2 = a * h2 + d, v3 = a * h3 + d;
            sum += (v0 + v1) + (v2 + v3);
            mx = fmaxf(mx, fmaxf(fmaxf(v0, v1), fmaxf(v2, v3)));
        }
        for (; r < e; r++) {
            float v = a * g_H[r * DK + c] + d;
            sum += v; mx = fmaxf(mx, v);
        }
        cnt = (float)(e - s);
    }
    g_Hg[g * 576 + c]          = sum / fmaxf(cnt, 1.f);
    g_Hg[g * 576 + DK + c]     = sum;
    g_Hg[g * 576 + 2 * DK + c] = mx;
}

// ================= K9: funnel head (bn2 + f1 + f2 + f3) =====================
// grid GG, block 384. bn2 stats recomputed per block (cheap, L2-resident).
__global__ void funnel_kernel(const float* __restrict__ g2, const float* __restrict__ be2,
                              const float* __restrict__ b1, const float* __restrict__ b2,
                              const float* __restrict__ w3, const float* __restrict__ b3,
                              float* __restrict__ out) {
    __shared__ float xs[576];
    __shared__ float o1s[384];
    __shared__ float o2s[192];
    int g = blockIdx.x, t = threadIdx.x;

    for (int c = t; c < 576; c += 384) {
        float s = 0.f, ss = 0.f;
        for (int gg = 0; gg < GG; gg++) {
            float v = g_Hg[gg * 576 + c];
            s += v; ss += v * v;
        }
        float m = s * (1.f / GG);
        float var = ss * (1.f / GG) - m * m;
        float rs = rsqrtf(var + 1e-5f);
        xs[c] = g2[c] * (g_Hg[g * 576 + c] - m) * rs + be2[c];
    }
    __syncthreads();

    {
        float a = b1[t];
        for (int k = 0; k < 576; k++) a += xs[k] * g_w1t[k * 384 + t];
        o1s[t] = fmaxf(a, 0.f);
    }
    __syncthreads();

    if (t < 192) {
        float a = b2[t];
        for (int k = 0; k < 384; k++) a += o1s[k] * g_w2t[k * 192 + t];
        o2s[t] = fmaxf(a, 0.f);
    }
    __syncthreads();

    if (t < 32) {
        int lane = t;
        float l = -INFINITY;
        if (lane < NC) {
            float a = b3[lane];
            for (int k = 0; k < 192; k++) a += o2s[k] * w3[lane * 192 + k];
            l = a;
        }
        float m = l;
        #pragma unroll
        for (int o = 16; o; o >>= 1) m = fmaxf(m, __shfl_xor_sync(0xffffffffu, m, o));
        float e = (lane < NC) ? expf(l - m) : 0.f;
        float s = e;
        #pragma unroll
        for (int o = 16; o; o >>= 1) s += __shfl_xor_sync(0xffffffffu, s, o);
        if (lane < NC) out[g * NC + lane] = l - m - logf(s);
    }
}

// ---------------- launch ----------------
extern "C" void kernel_launch(void* const* d_in, const int* in_sizes, int n_in,
                              void* d_out, int out_size) {
    const float* x     = (const float*)d_in[0];
    const void*  ei    = d_in[1];
    const void*  batch = d_in[2];
    const float* W     = (const float*)d_in[3];
    const float* b     = (const float*)d_in[4];
    const float* u     = (const float*)d_in[5];
    const float* g1    = (const float*)d_in[6];
    const float* be1   = (const float*)d_in[7];
    const float* g2    = (const float*)d_in[8];
    const float* be2   = (const float*)d_in[9];
    const float* w1    = (const float*)d_in[10];
    const float* b1    = (const float*)d_in[11];
    const float* w2    = (const float*)d_in[12];
    const float* b2    = (const float*)d_in[13];
    const float* w3    = (const float*)d_in[14];
    const float* b3    = (const float*)d_in[15];
    float* out = (float*)d_out;

    prep_kernel<<<TW_TOTAL / 256, 256>>>(ei, W, u, w1, w2);   // 1152 blocks
    deg_kernel<<<EE / 1024, 256>>>(ei, batch);                // 4 edges/thread + pos
    scan_kernel<<<1, 1024>>>();
    csr_kernel<<<EE / 1024, 256>>>(ei);                       // atomic-free scatter
    spmm_kernel<0><<<NN / 8, 256>>>(x);
    spmm_kernel<1><<<NN / 8, 256>>>(x);
    {
        dim3 grid(3, NN / 64);
        gemm_kernel<<<grid, 256>>>(x, b);
    }
    pool_kernel<<<GG, DK>>>(g1, be1);
    funnel_kernel<<<GG, 384>>>(g2, be2, b1, b2, w3, b3, out);
}